// round 15
// baseline (speedup 1.0000x reference)
#include <cuda_runtime.h>
#include <cuda_fp16.h>
#include <cuda_fp8.h>

#define NN 50000
#define EE 800000
#define E2T 850000   // EE + NN self loops
#define HH 4
#define CC 64
#define HC 256       // HH*CC

// Scratch (device globals; no allocation allowed; zero-init at module load)
__device__ unsigned char g_h8[NN * HC];  // fp8 (e4m3) head features for the edge gather
__device__ __half g_feath[NN * CC];      // fp16 layer output after gelu (next GEMM input)
__device__ __half g_wh1[128 * 256];      // fp16 W per layer
__device__ __half g_wh2[64 * 256];
__device__ __half g_wh3[64 * 256];
__device__ float  g_es[NN * HH];
__device__ float  g_ed[NN * HH];
__device__ float  g_ew[E2T * 4];         // per-edge softmax weights, CSR order
// CSR (built once per run; edge list identical across layers)
__device__ int g_cnt[NN];                // zeroed by scan1 after reading (replay-safe)
__device__ int g_off[NN + 1];
__device__ int g_cur[NN];
__device__ int g_csr[E2T];               // src indices grouped by dst
__device__ int g_csrd[E2T];              // dst index per csr slot (for ew_kernel)
__device__ int g_bsum[16];               // per-scan1-block sums

__device__ __forceinline__ float lrelu(float x) { return x >= 0.f ? x : 0.2f * x; }

// ---------------------------------------------------------------------------
// CSR build: hist (real edges, int4) -> scan1 (+1 self-loop per node, zeroes
// g_cnt) -> scan3 (bsum prefix + apply) -> scatter (src + dst per slot)
// ---------------------------------------------------------------------------
__global__ void hist_kernel(const int* __restrict__ ei) {
    int i4 = blockIdx.x * blockDim.x + threadIdx.x;
    if (i4 >= EE / 4) return;
    int4 d = ((const int4*)(ei + EE))[i4];
    atomicAdd(&g_cnt[d.x], 1);
    atomicAdd(&g_cnt[d.y], 1);
    atomicAdd(&g_cnt[d.z], 1);
    atomicAdd(&g_cnt[d.w], 1);
}

__global__ void scan1_kernel() {   // 13 blocks x 1024 threads, int4 per thread
    __shared__ int wsum[32];
    const int tid = threadIdx.x;
    const int lane = tid & 31, wid = tid >> 5;
    constexpr int N4 = NN / 4;  // 12500
    int i4 = blockIdx.x * 1024 + tid;
    int4 v = make_int4(0, 0, 0, 0);
    bool valid = i4 < N4;
    if (valid) {
        v = ((const int4*)g_cnt)[i4];
        ((int4*)g_cnt)[i4] = make_int4(0, 0, 0, 0);   // reset for next replay
        v.x += 1; v.y += 1; v.z += 1; v.w += 1;       // self loop per node
    }
    int tsum = v.x + v.y + v.z + v.w;
    int s = tsum;
#pragma unroll
    for (int o = 1; o < 32; o <<= 1) {
        int t = __shfl_up_sync(0xffffffffu, s, o);
        if (lane >= o) s += t;
    }
    if (lane == 31) wsum[wid] = s;
    __syncthreads();
    if (wid == 0) {
        int w = wsum[lane];
#pragma unroll
        for (int o = 1; o < 32; o <<= 1) {
            int t = __shfl_up_sync(0xffffffffu, w, o);
            if (lane >= o) w += t;
        }
        wsum[lane] = w;
        if (lane == 31) g_bsum[blockIdx.x] = w;   // block total
    }
    __syncthreads();
    int excl = s - tsum + (wid ? wsum[wid - 1] : 0);
    if (valid) {
        int4 o;
        o.x = excl;
        o.y = o.x + v.x;
        o.z = o.y + v.y;
        o.w = o.z + v.z;
        ((int4*)g_off)[i4] = o;
    }
}

__global__ void scan3_kernel() {   // per-block prefix of bsums, apply, fill g_cur
    __shared__ int s_add;
    constexpr int N4 = NN / 4;
    if (threadIdx.x < 32) {
        int v = ((int)threadIdx.x < (int)blockIdx.x) ? g_bsum[threadIdx.x] : 0;
#pragma unroll
        for (int o = 16; o > 0; o >>= 1) v += __shfl_xor_sync(0xffffffffu, v, o);
        if (threadIdx.x == 0) s_add = v;
    }
    __syncthreads();
    int add = s_add;
    int i4 = blockIdx.x * 1024 + threadIdx.x;
    if (i4 < N4) {
        int4 o = ((const int4*)g_off)[i4];
        o.x += add; o.y += add; o.z += add; o.w += add;
        ((int4*)g_off)[i4] = o;
        ((int4*)g_cur)[i4] = o;
    }
    if (i4 == 0) g_off[NN] = E2T;
}

__global__ void scatter_kernel(const int* __restrict__ ei) {
    int i4 = blockIdx.x * blockDim.x + threadIdx.x;
    if (i4 < EE / 4) {
        int4 s = ((const int4*)ei)[i4];
        int4 d = ((const int4*)(ei + EE))[i4];
        int p;
        p = atomicAdd(&g_cur[d.x], 1); g_csr[p] = s.x; g_csrd[p] = d.x;
        p = atomicAdd(&g_cur[d.y], 1); g_csr[p] = s.y; g_csrd[p] = d.y;
        p = atomicAdd(&g_cur[d.z], 1); g_csr[p] = s.z; g_csrd[p] = d.z;
        p = atomicAdd(&g_cur[d.w], 1); g_csr[p] = s.w; g_csrd[p] = d.w;
    } else if (i4 < E2T / 4) {
        int n0 = (i4 - EE / 4) * 4;   // self loops for nodes n0..n0+3
#pragma unroll
        for (int j = 0; j < 4; j++) {
            int n = n0 + j;
            int p = atomicAdd(&g_cur[n], 1);
            g_csr[p] = n;
            g_csrd[p] = n;
        }
    }
}

// ---------------------------------------------------------------------------
// Edge weights in CSR order (edge-parallel; huge MLP; coalesced write).
// Identical math to before: w = exp(lrelu(es[src]+ed[dst])), fp32.
// ---------------------------------------------------------------------------
__global__ void ew_kernel() {
    int e = blockIdx.x * blockDim.x + threadIdx.x;
    if (e >= E2T) return;
    int s = g_csr[e], d = g_csrd[e];
    float4 esv = __ldg((const float4*)&g_es[s * 4]);
    float4 edv = __ldg((const float4*)&g_ed[d * 4]);
    ((float4*)g_ew)[e] = make_float4(__expf(lrelu(esv.x + edv.x)),
                                     __expf(lrelu(esv.y + edv.y)),
                                     __expf(lrelu(esv.z + edv.z)),
                                     __expf(lrelu(esv.w + edv.w)));
}

// ---------------------------------------------------------------------------
// W fp32 -> fp16 (per-layer buffer)
// ---------------------------------------------------------------------------
__global__ void convw_kernel(const float* __restrict__ W, __half* __restrict__ Wh, int n) {
    int i = blockIdx.x * blockDim.x + threadIdx.x;
    if (i < n) Wh[i] = __float2half(W[i]);
}

// ---------------------------------------------------------------------------
// Tensor-core GEMM + attention epilogue.  M=64 tile, 256 threads / 8 warps.
// Warp w: head = w&3 (cols [64*head,64*head+64)), row-half = w>>2 (32 rows).
// C[NN,256] = A[NN,K] @ W[K,256], fp16 in, fp32 accum; predicated tail.
// Epilogue: fp8 h store + es/ed from fp32 accums, 4-lane shfl reduce.
// ---------------------------------------------------------------------------
template <bool F32>
__device__ __forceinline__ unsigned ldA(const void* A, int row, int col, int K, bool valid) {
    if (!valid) return 0u;
    if (F32) {
        float2 f = *(const float2*)((const float*)A + row * K + col);
        __half2 h = __floats2half2_rn(f.x, f.y);
        return *(unsigned*)&h;
    } else {
        return *(const unsigned*)((const __half*)A + row * K + col);
    }
}

template <int K, bool A_FP32>
__global__ void __launch_bounds__(256) hgemm_kernel(const void* __restrict__ Ain,
                                                    const __half* __restrict__ Wh,
                                                    const float* __restrict__ a_src,
                                                    const float* __restrict__ a_dst) {
    constexpr int KC = 64;            // k rows staged per chunk
    constexpr int NCH = K / KC;       // 2 (layer 1) or 1 (layers 2-3)
    constexpr int SBS = 264;          // smem stride in halves
    __shared__ __half sB[KC][SBS];

    const int tid = threadIdx.x;
    const int wfull = tid >> 5, lane = tid & 31;
    const int head = wfull & 3, rh = wfull >> 2;
    const int g = lane >> 2, tig = lane & 3;
    const int base = blockIdx.x * 64 + rh * 32;
    const int n0 = head * 64;

    const int r0 = base + g,      r1 = base + g + 8;
    const int r2 = base + g + 16, r3 = base + g + 24;
    const bool v0 = r0 < NN, v1 = r1 < NN, v2 = r2 < NN, v3 = r3 < NN;

    float c[2][8][4];
#pragma unroll
    for (int rg = 0; rg < 2; rg++)
#pragma unroll
        for (int j = 0; j < 8; j++)
#pragma unroll
            for (int q = 0; q < 4; q++) c[rg][j][q] = 0.f;

    for (int ch = 0; ch < NCH; ch++) {
        for (int idx = tid; idx < KC * 32; idx += 256) {
            int r = idx >> 5, c16 = idx & 31;
            *(uint4*)&sB[r][c16 * 8] =
                *(const uint4*)&Wh[(ch * KC + r) * 256 + c16 * 8];
        }
        __syncthreads();

#pragma unroll
        for (int kk = 0; kk < KC / 16; kk++) {
            const int kg = ch * KC + kk * 16;
            unsigned a0 = ldA<A_FP32>(Ain, r0, kg + 2 * tig,     K, v0);
            unsigned a1 = ldA<A_FP32>(Ain, r1, kg + 2 * tig,     K, v1);
            unsigned a2 = ldA<A_FP32>(Ain, r0, kg + 2 * tig + 8, K, v0);
            unsigned a3 = ldA<A_FP32>(Ain, r1, kg + 2 * tig + 8, K, v1);
            unsigned a4 = ldA<A_FP32>(Ain, r2, kg + 2 * tig,     K, v2);
            unsigned a5 = ldA<A_FP32>(Ain, r3, kg + 2 * tig,     K, v3);
            unsigned a6 = ldA<A_FP32>(Ain, r2, kg + 2 * tig + 8, K, v2);
            unsigned a7 = ldA<A_FP32>(Ain, r3, kg + 2 * tig + 8, K, v3);
#pragma unroll
            for (int jp = 0; jp < 4; jp++) {
                unsigned b0, b1, b2, b3;
                unsigned addr = (unsigned)__cvta_generic_to_shared(
                    &sB[kk * 16 + (lane & 15)][n0 + jp * 16 + (lane >> 4) * 8]);
                asm volatile(
                    "ldmatrix.sync.aligned.m8n8.x4.trans.shared.b16 {%0,%1,%2,%3}, [%4];"
                    : "=r"(b0), "=r"(b1), "=r"(b2), "=r"(b3) : "r"(addr));
                asm volatile(
                    "mma.sync.aligned.m16n8k16.row.col.f32.f16.f16.f32 "
                    "{%0,%1,%2,%3}, {%4,%5,%6,%7}, {%8,%9}, {%0,%1,%2,%3};"
                    : "+f"(c[0][2*jp][0]), "+f"(c[0][2*jp][1]), "+f"(c[0][2*jp][2]), "+f"(c[0][2*jp][3])
                    : "r"(a0), "r"(a1), "r"(a2), "r"(a3), "r"(b0), "r"(b1));
                asm volatile(
                    "mma.sync.aligned.m16n8k16.row.col.f32.f16.f16.f32 "
                    "{%0,%1,%2,%3}, {%4,%5,%6,%7}, {%8,%9}, {%0,%1,%2,%3};"
                    : "+f"(c[0][2*jp+1][0]), "+f"(c[0][2*jp+1][1]), "+f"(c[0][2*jp+1][2]), "+f"(c[0][2*jp+1][3])
                    : "r"(a0), "r"(a1), "r"(a2), "r"(a3), "r"(b2), "r"(b3));
                asm volatile(
                    "mma.sync.aligned.m16n8k16.row.col.f32.f16.f16.f32 "
                    "{%0,%1,%2,%3}, {%4,%5,%6,%7}, {%8,%9}, {%0,%1,%2,%3};"
                    : "+f"(c[1][2*jp][0]), "+f"(c[1][2*jp][1]), "+f"(c[1][2*jp][2]), "+f"(c[1][2*jp][3])
                    : "r"(a4), "r"(a5), "r"(a6), "r"(a7), "r"(b0), "r"(b1));
                asm volatile(
                    "mma.sync.aligned.m16n8k16.row.col.f32.f16.f16.f32 "
                    "{%0,%1,%2,%3}, {%4,%5,%6,%7}, {%8,%9}, {%0,%1,%2,%3};"
                    : "+f"(c[1][2*jp+1][0]), "+f"(c[1][2*jp+1][1]), "+f"(c[1][2*jp+1][2]), "+f"(c[1][2*jp+1][3])
                    : "r"(a4), "r"(a5), "r"(a6), "r"(a7), "r"(b2), "r"(b3));
            }
        }
        __syncthreads();
    }

    // Epilogue: fp8 h store + es/ed partials
    float ps[4] = {0.f, 0.f, 0.f, 0.f};
    float pd[4] = {0.f, 0.f, 0.f, 0.f};
#pragma unroll
    for (int j = 0; j < 8; j++) {
        int col = n0 + 8 * j + 2 * tig;
        float2 as2 = *(const float2*)&a_src[col];
        float2 ad2 = *(const float2*)&a_dst[col];
#pragma unroll
        for (int rg = 0; rg < 2; rg++) {
            int rowA = base + 16 * rg + g, rowB = rowA + 8;
            __nv_fp8x2_storage_t p0 = __nv_cvt_float2_to_fp8x2(
                make_float2(c[rg][j][0], c[rg][j][1]), __NV_SATFINITE, __NV_E4M3);
            __nv_fp8x2_storage_t p1 = __nv_cvt_float2_to_fp8x2(
                make_float2(c[rg][j][2], c[rg][j][3]), __NV_SATFINITE, __NV_E4M3);
            if (rowA < NN) *(unsigned short*)&g_h8[rowA * HC + col] = p0;
            if (rowB < NN) *(unsigned short*)&g_h8[rowB * HC + col] = p1;
            ps[2*rg]   += c[rg][j][0] * as2.x + c[rg][j][1] * as2.y;
            pd[2*rg]   += c[rg][j][0] * ad2.x + c[rg][j][1] * ad2.y;
            ps[2*rg+1] += c[rg][j][2] * as2.x + c[rg][j][3] * as2.y;
            pd[2*rg+1] += c[rg][j][2] * ad2.x + c[rg][j][3] * ad2.y;
        }
    }
#pragma unroll
    for (int o = 1; o <= 2; o <<= 1) {
#pragma unroll
        for (int q = 0; q < 4; q++) {
            ps[q] += __shfl_xor_sync(0xffffffffu, ps[q], o);
            pd[q] += __shfl_xor_sync(0xffffffffu, pd[q], o);
        }
    }
    if (tig == 0) {
        const int rows[4] = {r0, r1, r2, r3};
#pragma unroll
        for (int q = 0; q < 4; q++) {
            if (rows[q] < NN) {
                g_es[rows[q] * HH + head] = ps[q];
                g_ed[rows[q] * HH + head] = pd[q];
            }
        }
    }
}

// ---------------------------------------------------------------------------
// Fused softmax-aggregate + normalize + head-mean + bias + gelu.
// Warp per dst node (8/block). Lane t owns channels 8t..8t+7 (fp8, 8B/edge).
// Weights read precomputed from g_ew (coalesced; no random es gather, no exp,
// no dependency chain). FINAL: fuse fc dot + sigmoid -> d_out.
// ---------------------------------------------------------------------------
template <bool FINAL>
__global__ void __launch_bounds__(256) aggregate_kernel(const float* __restrict__ bias,
                                                        const float* __restrict__ fcW,
                                                        const float* __restrict__ fcb,
                                                        float* __restrict__ out) {
    __shared__ int    ss[8][32];
    __shared__ float4 ws[8][32];

    const int wid = threadIdx.x >> 5;
    const int lid = threadIdx.x & 31;
    const int n = blockIdx.x * 8 + wid;   // NN == 6250 * 8
    const int head = lid >> 3;

    const int row0 = g_off[n], row1 = g_off[n + 1];

    float acc[8] = {0.f, 0.f, 0.f, 0.f, 0.f, 0.f, 0.f, 0.f};
    float dsum = 0.f;

    for (int base = row0; base < row1; base += 32) {
        int cnt = min(32, row1 - base);
        if (lid < cnt) {
            ss[wid][lid] = __ldg(&g_csr[base + lid]) * HC;
            ws[wid][lid] = __ldg((const float4*)&g_ew[4 * (base + lid)]);
        }
        __syncwarp();
#pragma unroll 4
        for (int e = 0; e < cnt; e++) {
            float wv = ((const float*)&ws[wid][e])[head];
            uint2 hv = *(const uint2*)&g_h8[ss[wid][e] + 8 * lid];
            __half2_raw r0 = __nv_cvt_fp8x2_to_halfraw2((__nv_fp8x2_storage_t)(hv.x),
                                                        __NV_E4M3);
            __half2_raw r1 = __nv_cvt_fp8x2_to_halfraw2((__nv_fp8x2_storage_t)(hv.x >> 16),
                                                        __NV_E4M3);
            __half2_raw r2 = __nv_cvt_fp8x2_to_halfraw2((__nv_fp8x2_storage_t)(hv.y),
                                                        __NV_E4M3);
            __half2_raw r3 = __nv_cvt_fp8x2_to_halfraw2((__nv_fp8x2_storage_t)(hv.y >> 16),
                                                        __NV_E4M3);
            float2 f0 = __half22float2(*(__half2*)&r0);
            float2 f1 = __half22float2(*(__half2*)&r1);
            float2 f2 = __half22float2(*(__half2*)&r2);
            float2 f3 = __half22float2(*(__half2*)&r3);
            acc[0] += wv * f0.x; acc[1] += wv * f0.y;
            acc[2] += wv * f1.x; acc[3] += wv * f1.y;
            acc[4] += wv * f2.x; acc[5] += wv * f2.y;
            acc[6] += wv * f3.x; acc[7] += wv * f3.y;
            dsum += wv;
        }
        __syncwarp();
    }

    float inv = 1.f / (dsum + 1e-16f);
#pragma unroll
    for (int i = 0; i < 8; i++) {
        acc[i] *= inv;
        acc[i] += __shfl_xor_sync(0xffffffffu, acc[i], 8);
        acc[i] += __shfl_xor_sync(0xffffffffu, acc[i], 16);
    }
    // lanes 0..7 hold head-sums for channels 8*lid..8*lid+7
    if (lid < 8) {
        float gl[8];
#pragma unroll
        for (int i = 0; i < 8; i++) {
            float s = 0.25f * acc[i] + bias[8 * lid + i];
            float t = tanhf(0.7978845608028654f * (s + 0.044715f * s * s * s));
            gl[i] = 0.5f * s * (1.f + t);
        }
        if (FINAL) {
            float p = 0.f;
#pragma unroll
            for (int i = 0; i < 8; i++) p += gl[i] * fcW[8 * lid + i];
#pragma unroll
            for (int o = 1; o <= 4; o <<= 1)
                p += __shfl_xor_sync(0xffu, p, o);
            if (lid == 0) out[n] = 1.f / (1.f + __expf(-(p + fcb[0])));
        } else {
            __half2 outh[4];
#pragma unroll
            for (int i = 0; i < 8; i += 2)
                outh[i >> 1] = __floats2half2_rn(gl[i], gl[i + 1]);
            *(uint4*)&g_feath[n * CC + 8 * lid] = *(uint4*)outh;
        }
    }
}

// ---------------------------------------------------------------------------

extern "C" void kernel_launch(void* const* d_in, const int* in_sizes, int n_in,
                              void* d_out, int out_size) {
    const float* x    = (const float*)d_in[0];
    const int*   ei   = (const int*)d_in[1];
    const float* W1   = (const float*)d_in[2];
    const float* as1  = (const float*)d_in[3];
    const float* ad1  = (const float*)d_in[4];
    const float* b1   = (const float*)d_in[5];
    const float* W2   = (const float*)d_in[6];
    const float* as2  = (const float*)d_in[7];
    const float* ad2  = (const float*)d_in[8];
    const float* b2   = (const float*)d_in[9];
    const float* W3   = (const float*)d_in[10];
    const float* as3  = (const float*)d_in[11];
    const float* ad3  = (const float*)d_in[12];
    const float* b3   = (const float*)d_in[13];
    const float* fcW  = (const float*)d_in[14];
    const float* fcb  = (const float*)d_in[15];

    __half *feath_ptr = nullptr, *wh1 = nullptr, *wh2 = nullptr, *wh3 = nullptr;
    cudaGetSymbolAddress((void**)&feath_ptr, g_feath);
    cudaGetSymbolAddress((void**)&wh1, g_wh1);
    cudaGetSymbolAddress((void**)&wh2, g_wh2);
    cudaGetSymbolAddress((void**)&wh3, g_wh3);

    // Fork: CSR build on side stream, overlapped with layer-1 convw+GEMM.
    cudaStream_t s2;
    cudaStreamCreateWithFlags(&s2, cudaStreamNonBlocking);
    cudaEvent_t evFork, evJoin, evW;
    cudaEventCreateWithFlags(&evFork, cudaEventDisableTiming);
    cudaEventCreateWithFlags(&evJoin, cudaEventDisableTiming);
    cudaEventCreateWithFlags(&evW, cudaEventDisableTiming);

    cudaEventRecord(evFork, 0);
    cudaStreamWaitEvent(s2, evFork, 0);
    hist_kernel<<<(EE / 4 + 255) / 256, 256, 0, s2>>>(ei);
    scan1_kernel<<<13, 1024, 0, s2>>>();
    scan3_kernel<<<13, 1024, 0, s2>>>();
    scatter_kernel<<<(E2T / 4 + 255) / 256, 256, 0, s2>>>(ei);
    cudaEventRecord(evJoin, s2);
    // W2/W3 conversion after the join point; gated separately before hgemm2.
    convw_kernel<<<(64 * 256 + 255) / 256, 256, 0, s2>>>(W2, wh2, 64 * 256);
    convw_kernel<<<(64 * 256 + 255) / 256, 256, 0, s2>>>(W3, wh3, 64 * 256);
    cudaEventRecord(evW, s2);

    // Layer 1 (independent of CSR)
    convw_kernel<<<(128 * 256 + 255) / 256, 256>>>(W1, wh1, 128 * 256);
    hgemm_kernel<128, true><<<(NN + 63) / 64, 256>>>(x, wh1, as1, ad1);

    cudaStreamWaitEvent(0, evJoin, 0);
    ew_kernel<<<(E2T + 255) / 256, 256>>>();
    aggregate_kernel<false><<<NN / 8, 256>>>(b1, nullptr, nullptr, nullptr);

    cudaStreamWaitEvent(0, evW, 0);
    hgemm_kernel<64, false><<<(NN + 63) / 64, 256>>>(feath_ptr, wh2, as2, ad2);
    ew_kernel<<<(E2T + 255) / 256, 256>>>();
    aggregate_kernel<false><<<NN / 8, 256>>>(b2, nullptr, nullptr, nullptr);

    hgemm_kernel<64, false><<<(NN + 63) / 64, 256>>>(feath_ptr, wh3, as3, ad3);
    ew_kernel<<<(E2T + 255) / 256, 256>>>();
    aggregate_kernel<true><<<NN / 8, 256>>>(b3, fcW, fcb, (float*)d_out);

    cudaStreamDestroy(s2);
    cudaEventDestroy(evFork);
    cudaEventDestroy(evJoin);
    cudaEventDestroy(evW);
}

// round 16
// speedup vs baseline: 1.1024x; 1.1024x over previous
#include <cuda_runtime.h>
#include <cuda_fp16.h>
#include <cuda_fp8.h>

#define NN 50000
#define EE 800000
#define E2T 850000   // EE + NN self loops
#define HH 4
#define CC 64
#define HC 256       // HH*CC

// Scratch (device globals; no allocation allowed; zero-init at module load)
__device__ unsigned char g_h8[NN * HC];  // fp8 (e4m3) head features for the edge gather
__device__ __half g_feath[NN * CC];      // fp16 layer output after gelu (next GEMM input)
__device__ __half g_wh1[128 * 256];      // fp16 W per layer
__device__ __half g_wh2[64 * 256];
__device__ __half g_wh3[64 * 256];
__device__ float  g_es[NN * HH];
__device__ float  g_ed[NN * HH];
// CSR (built once per run; edge list identical across layers)
__device__ int g_cnt[NN];                // zeroed by scan1 after reading (replay-safe)
__device__ int g_off[NN + 1];
__device__ int g_cur[NN];
__device__ int g_csr[E2T];               // src indices grouped by dst
__device__ int g_bsum[16];               // per-scan1-block sums

__device__ __forceinline__ float lrelu(float x) { return x >= 0.f ? x : 0.2f * x; }

// ---------------------------------------------------------------------------
// CSR build: hist (real edges, int4) -> scan1 (+1 self-loop per node, zeroes
// g_cnt) -> scan3 (bsum prefix + apply) -> scatter (int4 + self loops)
// ---------------------------------------------------------------------------
__global__ void hist_kernel(const int* __restrict__ ei) {
    int i4 = blockIdx.x * blockDim.x + threadIdx.x;
    if (i4 >= EE / 4) return;
    int4 d = ((const int4*)(ei + EE))[i4];
    atomicAdd(&g_cnt[d.x], 1);
    atomicAdd(&g_cnt[d.y], 1);
    atomicAdd(&g_cnt[d.z], 1);
    atomicAdd(&g_cnt[d.w], 1);
}

__global__ void scan1_kernel() {   // 13 blocks x 1024 threads, int4 per thread
    __shared__ int wsum[32];
    const int tid = threadIdx.x;
    const int lane = tid & 31, wid = tid >> 5;
    constexpr int N4 = NN / 4;  // 12500
    int i4 = blockIdx.x * 1024 + tid;
    int4 v = make_int4(0, 0, 0, 0);
    bool valid = i4 < N4;
    if (valid) {
        v = ((const int4*)g_cnt)[i4];
        ((int4*)g_cnt)[i4] = make_int4(0, 0, 0, 0);   // reset for next replay
        v.x += 1; v.y += 1; v.z += 1; v.w += 1;       // self loop per node
    }
    int tsum = v.x + v.y + v.z + v.w;
    int s = tsum;
#pragma unroll
    for (int o = 1; o < 32; o <<= 1) {
        int t = __shfl_up_sync(0xffffffffu, s, o);
        if (lane >= o) s += t;
    }
    if (lane == 31) wsum[wid] = s;
    __syncthreads();
    if (wid == 0) {
        int w = wsum[lane];
#pragma unroll
        for (int o = 1; o < 32; o <<= 1) {
            int t = __shfl_up_sync(0xffffffffu, w, o);
            if (lane >= o) w += t;
        }
        wsum[lane] = w;
        if (lane == 31) g_bsum[blockIdx.x] = w;   // block total
    }
    __syncthreads();
    int excl = s - tsum + (wid ? wsum[wid - 1] : 0);
    if (valid) {
        int4 o;
        o.x = excl;
        o.y = o.x + v.x;
        o.z = o.y + v.y;
        o.w = o.z + v.z;
        ((int4*)g_off)[i4] = o;
    }
}

__global__ void scan3_kernel() {   // per-block prefix of bsums, apply, fill g_cur
    __shared__ int s_add;
    constexpr int N4 = NN / 4;
    if (threadIdx.x < 32) {
        int v = ((int)threadIdx.x < (int)blockIdx.x) ? g_bsum[threadIdx.x] : 0;
#pragma unroll
        for (int o = 16; o > 0; o >>= 1) v += __shfl_xor_sync(0xffffffffu, v, o);
        if (threadIdx.x == 0) s_add = v;
    }
    __syncthreads();
    int add = s_add;
    int i4 = blockIdx.x * 1024 + threadIdx.x;
    if (i4 < N4) {
        int4 o = ((const int4*)g_off)[i4];
        o.x += add; o.y += add; o.z += add; o.w += add;
        ((int4*)g_off)[i4] = o;
        ((int4*)g_cur)[i4] = o;
    }
    if (i4 == 0) g_off[NN] = E2T;
}

__global__ void scatter_kernel(const int* __restrict__ ei) {
    int i4 = blockIdx.x * blockDim.x + threadIdx.x;
    if (i4 < EE / 4) {
        int4 s = ((const int4*)ei)[i4];
        int4 d = ((const int4*)(ei + EE))[i4];
        int p;
        p = atomicAdd(&g_cur[d.x], 1); g_csr[p] = s.x;
        p = atomicAdd(&g_cur[d.y], 1); g_csr[p] = s.y;
        p = atomicAdd(&g_cur[d.z], 1); g_csr[p] = s.z;
        p = atomicAdd(&g_cur[d.w], 1); g_csr[p] = s.w;
    } else if (i4 < E2T / 4) {
        int n0 = (i4 - EE / 4) * 4;   // self loops for nodes n0..n0+3
#pragma unroll
        for (int j = 0; j < 4; j++) {
            int n = n0 + j;
            int p = atomicAdd(&g_cur[n], 1);
            g_csr[p] = n;
        }
    }
}

// ---------------------------------------------------------------------------
// W fp32 -> fp16 (per-layer buffer)
// ---------------------------------------------------------------------------
__global__ void convw_kernel(const float* __restrict__ W, __half* __restrict__ Wh, int n) {
    int i = blockIdx.x * blockDim.x + threadIdx.x;
    if (i < n) Wh[i] = __float2half(W[i]);
}

// ---------------------------------------------------------------------------
// Tensor-core GEMM + attention epilogue.  M=64 tile, 256 threads / 8 warps.
// Warp w: head = w&3 (cols [64*head,64*head+64)), row-half = w>>2 (32 rows).
// C[NN,256] = A[NN,K] @ W[K,256], fp16 in, fp32 accum; predicated tail.
// Epilogue: fp8 h store + es/ed from fp32 accums, 4-lane shfl reduce.
// ---------------------------------------------------------------------------
template <bool F32>
__device__ __forceinline__ unsigned ldA(const void* A, int row, int col, int K, bool valid) {
    if (!valid) return 0u;
    if (F32) {
        float2 f = *(const float2*)((const float*)A + row * K + col);
        __half2 h = __floats2half2_rn(f.x, f.y);
        return *(unsigned*)&h;
    } else {
        return *(const unsigned*)((const __half*)A + row * K + col);
    }
}

template <int K, bool A_FP32>
__global__ void __launch_bounds__(256) hgemm_kernel(const void* __restrict__ Ain,
                                                    const __half* __restrict__ Wh,
                                                    const float* __restrict__ a_src,
                                                    const float* __restrict__ a_dst) {
    constexpr int KC = 64;            // k rows staged per chunk
    constexpr int NCH = K / KC;       // 2 (layer 1) or 1 (layers 2-3)
    constexpr int SBS = 264;          // smem stride in halves
    __shared__ __half sB[KC][SBS];

    const int tid = threadIdx.x;
    const int wfull = tid >> 5, lane = tid & 31;
    const int head = wfull & 3, rh = wfull >> 2;
    const int g = lane >> 2, tig = lane & 3;
    const int base = blockIdx.x * 64 + rh * 32;
    const int n0 = head * 64;

    const int r0 = base + g,      r1 = base + g + 8;
    const int r2 = base + g + 16, r3 = base + g + 24;
    const bool v0 = r0 < NN, v1 = r1 < NN, v2 = r2 < NN, v3 = r3 < NN;

    float c[2][8][4];
#pragma unroll
    for (int rg = 0; rg < 2; rg++)
#pragma unroll
        for (int j = 0; j < 8; j++)
#pragma unroll
            for (int q = 0; q < 4; q++) c[rg][j][q] = 0.f;

    for (int ch = 0; ch < NCH; ch++) {
        for (int idx = tid; idx < KC * 32; idx += 256) {
            int r = idx >> 5, c16 = idx & 31;
            *(uint4*)&sB[r][c16 * 8] =
                *(const uint4*)&Wh[(ch * KC + r) * 256 + c16 * 8];
        }
        __syncthreads();

#pragma unroll
        for (int kk = 0; kk < KC / 16; kk++) {
            const int kg = ch * KC + kk * 16;
            unsigned a0 = ldA<A_FP32>(Ain, r0, kg + 2 * tig,     K, v0);
            unsigned a1 = ldA<A_FP32>(Ain, r1, kg + 2 * tig,     K, v1);
            unsigned a2 = ldA<A_FP32>(Ain, r0, kg + 2 * tig + 8, K, v0);
            unsigned a3 = ldA<A_FP32>(Ain, r1, kg + 2 * tig + 8, K, v1);
            unsigned a4 = ldA<A_FP32>(Ain, r2, kg + 2 * tig,     K, v2);
            unsigned a5 = ldA<A_FP32>(Ain, r3, kg + 2 * tig,     K, v3);
            unsigned a6 = ldA<A_FP32>(Ain, r2, kg + 2 * tig + 8, K, v2);
            unsigned a7 = ldA<A_FP32>(Ain, r3, kg + 2 * tig + 8, K, v3);
#pragma unroll
            for (int jp = 0; jp < 4; jp++) {
                unsigned b0, b1, b2, b3;
                unsigned addr = (unsigned)__cvta_generic_to_shared(
                    &sB[kk * 16 + (lane & 15)][n0 + jp * 16 + (lane >> 4) * 8]);
                asm volatile(
                    "ldmatrix.sync.aligned.m8n8.x4.trans.shared.b16 {%0,%1,%2,%3}, [%4];"
                    : "=r"(b0), "=r"(b1), "=r"(b2), "=r"(b3) : "r"(addr));
                asm volatile(
                    "mma.sync.aligned.m16n8k16.row.col.f32.f16.f16.f32 "
                    "{%0,%1,%2,%3}, {%4,%5,%6,%7}, {%8,%9}, {%0,%1,%2,%3};"
                    : "+f"(c[0][2*jp][0]), "+f"(c[0][2*jp][1]), "+f"(c[0][2*jp][2]), "+f"(c[0][2*jp][3])
                    : "r"(a0), "r"(a1), "r"(a2), "r"(a3), "r"(b0), "r"(b1));
                asm volatile(
                    "mma.sync.aligned.m16n8k16.row.col.f32.f16.f16.f32 "
                    "{%0,%1,%2,%3}, {%4,%5,%6,%7}, {%8,%9}, {%0,%1,%2,%3};"
                    : "+f"(c[0][2*jp+1][0]), "+f"(c[0][2*jp+1][1]), "+f"(c[0][2*jp+1][2]), "+f"(c[0][2*jp+1][3])
                    : "r"(a0), "r"(a1), "r"(a2), "r"(a3), "r"(b2), "r"(b3));
                asm volatile(
                    "mma.sync.aligned.m16n8k16.row.col.f32.f16.f16.f32 "
                    "{%0,%1,%2,%3}, {%4,%5,%6,%7}, {%8,%9}, {%0,%1,%2,%3};"
                    : "+f"(c[1][2*jp][0]), "+f"(c[1][2*jp][1]), "+f"(c[1][2*jp][2]), "+f"(c[1][2*jp][3])
                    : "r"(a4), "r"(a5), "r"(a6), "r"(a7), "r"(b0), "r"(b1));
                asm volatile(
                    "mma.sync.aligned.m16n8k16.row.col.f32.f16.f16.f32 "
                    "{%0,%1,%2,%3}, {%4,%5,%6,%7}, {%8,%9}, {%0,%1,%2,%3};"
                    : "+f"(c[1][2*jp+1][0]), "+f"(c[1][2*jp+1][1]), "+f"(c[1][2*jp+1][2]), "+f"(c[1][2*jp+1][3])
                    : "r"(a4), "r"(a5), "r"(a6), "r"(a7), "r"(b2), "r"(b3));
            }
        }
        __syncthreads();
    }

    // Epilogue: fp8 h store + es/ed partials
    float ps[4] = {0.f, 0.f, 0.f, 0.f};
    float pd[4] = {0.f, 0.f, 0.f, 0.f};
#pragma unroll
    for (int j = 0; j < 8; j++) {
        int col = n0 + 8 * j + 2 * tig;
        float2 as2 = *(const float2*)&a_src[col];
        float2 ad2 = *(const float2*)&a_dst[col];
#pragma unroll
        for (int rg = 0; rg < 2; rg++) {
            int rowA = base + 16 * rg + g, rowB = rowA + 8;
            __nv_fp8x2_storage_t p0 = __nv_cvt_float2_to_fp8x2(
                make_float2(c[rg][j][0], c[rg][j][1]), __NV_SATFINITE, __NV_E4M3);
            __nv_fp8x2_storage_t p1 = __nv_cvt_float2_to_fp8x2(
                make_float2(c[rg][j][2], c[rg][j][3]), __NV_SATFINITE, __NV_E4M3);
            if (rowA < NN) *(unsigned short*)&g_h8[rowA * HC + col] = p0;
            if (rowB < NN) *(unsigned short*)&g_h8[rowB * HC + col] = p1;
            ps[2*rg]   += c[rg][j][0] * as2.x + c[rg][j][1] * as2.y;
            pd[2*rg]   += c[rg][j][0] * ad2.x + c[rg][j][1] * ad2.y;
            ps[2*rg+1] += c[rg][j][2] * as2.x + c[rg][j][3] * as2.y;
            pd[2*rg+1] += c[rg][j][2] * ad2.x + c[rg][j][3] * ad2.y;
        }
    }
#pragma unroll
    for (int o = 1; o <= 2; o <<= 1) {
#pragma unroll
        for (int q = 0; q < 4; q++) {
            ps[q] += __shfl_xor_sync(0xffffffffu, ps[q], o);
            pd[q] += __shfl_xor_sync(0xffffffffu, pd[q], o);
        }
    }
    if (tig == 0) {
        const int rows[4] = {r0, r1, r2, r3};
#pragma unroll
        for (int q = 0; q < 4; q++) {
            if (rows[q] < NN) {
                g_es[rows[q] * HH + head] = ps[q];
                g_ed[rows[q] * HH + head] = pd[q];
            }
        }
    }
}

// ---------------------------------------------------------------------------
// Fused softmax-aggregate + normalize + head-mean + bias + gelu.
// Warp per dst node (8/block). Lane t owns channels 8t..8t+7 (fp8, 8B/edge).
// Single pass: alpha = exp(e)/sum exp(e). FINAL: fuse fc dot + sigmoid.
// ---------------------------------------------------------------------------
template <bool FINAL>
__global__ void __launch_bounds__(256) aggregate_kernel(const float* __restrict__ bias,
                                                        const float* __restrict__ fcW,
                                                        const float* __restrict__ fcb,
                                                        float* __restrict__ out) {
    __shared__ int    ss[8][32];
    __shared__ float4 ws[8][32];

    const int wid = threadIdx.x >> 5;
    const int lid = threadIdx.x & 31;
    const int n = blockIdx.x * 8 + wid;   // NN == 6250 * 8
    const int head = lid >> 3;

    const int row0 = g_off[n], row1 = g_off[n + 1];
    const float4 edv = *(const float4*)&g_ed[n * 4];

    float acc[8] = {0.f, 0.f, 0.f, 0.f, 0.f, 0.f, 0.f, 0.f};
    float dsum = 0.f;

    for (int base = row0; base < row1; base += 32) {
        int cnt = min(32, row1 - base);
        if (lid < cnt) {
            int s = __ldg(&g_csr[base + lid]);
            ss[wid][lid] = s * HC;
            float4 esv = __ldg((const float4*)&g_es[s * 4]);
            ws[wid][lid] = make_float4(__expf(lrelu(esv.x + edv.x)),
                                       __expf(lrelu(esv.y + edv.y)),
                                       __expf(lrelu(esv.z + edv.z)),
                                       __expf(lrelu(esv.w + edv.w)));
        }
        __syncwarp();
#pragma unroll 4
        for (int e = 0; e < cnt; e++) {
            float wv = ((const float*)&ws[wid][e])[head];
            uint2 hv = *(const uint2*)&g_h8[ss[wid][e] + 8 * lid];
            __half2_raw r0 = __nv_cvt_fp8x2_to_halfraw2((__nv_fp8x2_storage_t)(hv.x),
                                                        __NV_E4M3);
            __half2_raw r1 = __nv_cvt_fp8x2_to_halfraw2((__nv_fp8x2_storage_t)(hv.x >> 16),
                                                        __NV_E4M3);
            __half2_raw r2 = __nv_cvt_fp8x2_to_halfraw2((__nv_fp8x2_storage_t)(hv.y),
                                                        __NV_E4M3);
            __half2_raw r3 = __nv_cvt_fp8x2_to_halfraw2((__nv_fp8x2_storage_t)(hv.y >> 16),
                                                        __NV_E4M3);
            float2 f0 = __half22float2(*(__half2*)&r0);
            float2 f1 = __half22float2(*(__half2*)&r1);
            float2 f2 = __half22float2(*(__half2*)&r2);
            float2 f3 = __half22float2(*(__half2*)&r3);
            acc[0] += wv * f0.x; acc[1] += wv * f0.y;
            acc[2] += wv * f1.x; acc[3] += wv * f1.y;
            acc[4] += wv * f2.x; acc[5] += wv * f2.y;
            acc[6] += wv * f3.x; acc[7] += wv * f3.y;
            dsum += wv;
        }
        __syncwarp();
    }

    float inv = 1.f / (dsum + 1e-16f);
#pragma unroll
    for (int i = 0; i < 8; i++) {
        acc[i] *= inv;
        acc[i] += __shfl_xor_sync(0xffffffffu, acc[i], 8);
        acc[i] += __shfl_xor_sync(0xffffffffu, acc[i], 16);
    }
    // lanes 0..7 hold head-sums for channels 8*lid..8*lid+7
    if (lid < 8) {
        float gl[8];
#pragma unroll
        for (int i = 0; i < 8; i++) {
            float s = 0.25f * acc[i] + bias[8 * lid + i];
            float t = tanhf(0.7978845608028654f * (s + 0.044715f * s * s * s));
            gl[i] = 0.5f * s * (1.f + t);
        }
        if (FINAL) {
            float p = 0.f;
#pragma unroll
            for (int i = 0; i < 8; i++) p += gl[i] * fcW[8 * lid + i];
#pragma unroll
            for (int o = 1; o <= 4; o <<= 1)
                p += __shfl_xor_sync(0xffu, p, o);
            if (lid == 0) out[n] = 1.f / (1.f + __expf(-(p + fcb[0])));
        } else {
            __half2 outh[4];
#pragma unroll
            for (int i = 0; i < 8; i += 2)
                outh[i >> 1] = __floats2half2_rn(gl[i], gl[i + 1]);
            *(uint4*)&g_feath[n * CC + 8 * lid] = *(uint4*)outh;
        }
    }
}

// ---------------------------------------------------------------------------

extern "C" void kernel_launch(void* const* d_in, const int* in_sizes, int n_in,
                              void* d_out, int out_size) {
    const float* x    = (const float*)d_in[0];
    const int*   ei   = (const int*)d_in[1];
    const float* W1   = (const float*)d_in[2];
    const float* as1  = (const float*)d_in[3];
    const float* ad1  = (const float*)d_in[4];
    const float* b1   = (const float*)d_in[5];
    const float* W2   = (const float*)d_in[6];
    const float* as2  = (const float*)d_in[7];
    const float* ad2  = (const float*)d_in[8];
    const float* b2   = (const float*)d_in[9];
    const float* W3   = (const float*)d_in[10];
    const float* as3  = (const float*)d_in[11];
    const float* ad3  = (const float*)d_in[12];
    const float* b3   = (const float*)d_in[13];
    const float* fcW  = (const float*)d_in[14];
    const float* fcb  = (const float*)d_in[15];

    __half *feath_ptr = nullptr, *wh1 = nullptr, *wh2 = nullptr, *wh3 = nullptr;
    cudaGetSymbolAddress((void**)&feath_ptr, g_feath);
    cudaGetSymbolAddress((void**)&wh1, g_wh1);
    cudaGetSymbolAddress((void**)&wh2, g_wh2);
    cudaGetSymbolAddress((void**)&wh3, g_wh3);

    // Fork: CSR build on side stream, overlapped with layer-1 convw+GEMM.
    // Submission order interleaved so hgemm1 is the 4th submitted kernel
    // (ncu -s/-c lands on it); execution semantics identical.
    cudaStream_t s2;
    cudaStreamCreateWithFlags(&s2, cudaStreamNonBlocking);
    cudaEvent_t evFork, evJoin, evW;
    cudaEventCreateWithFlags(&evFork, cudaEventDisableTiming);
    cudaEventCreateWithFlags(&evJoin, cudaEventDisableTiming);
    cudaEventCreateWithFlags(&evW, cudaEventDisableTiming);

    cudaEventRecord(evFork, 0);
    cudaStreamWaitEvent(s2, evFork, 0);

    convw_kernel<<<(128 * 256 + 255) / 256, 256>>>(W1, wh1, 128 * 256);      // #1 (main)
    hist_kernel<<<(EE / 4 + 255) / 256, 256, 0, s2>>>(ei);                   // #2 (s2)
    scan1_kernel<<<13, 1024, 0, s2>>>();                                     // #3 (s2)
    hgemm_kernel<128, true><<<(NN + 63) / 64, 256>>>(x, wh1, as1, ad1);      // #4 (main) <- profiled
    scan3_kernel<<<13, 1024, 0, s2>>>();                                     // #5 (s2)
    scatter_kernel<<<(E2T / 4 + 255) / 256, 256, 0, s2>>>(ei);               // #6 (s2)
    cudaEventRecord(evJoin, s2);
    convw_kernel<<<(64 * 256 + 255) / 256, 256, 0, s2>>>(W2, wh2, 64 * 256); // #7 (s2)
    convw_kernel<<<(64 * 256 + 255) / 256, 256, 0, s2>>>(W3, wh3, 64 * 256); // #8 (s2)
    cudaEventRecord(evW, s2);

    cudaStreamWaitEvent(0, evJoin, 0);
    aggregate_kernel<false><<<NN / 8, 256>>>(b1, nullptr, nullptr, nullptr);

    cudaStreamWaitEvent(0, evW, 0);
    hgemm_kernel<64, false><<<(NN + 63) / 64, 256>>>(feath_ptr, wh2, as2, ad2);
    aggregate_kernel<false><<<NN / 8, 256>>>(b2, nullptr, nullptr, nullptr);

    hgemm_kernel<64, false><<<(NN + 63) / 64, 256>>>(feath_ptr, wh3, as3, ad3);
    aggregate_kernel<true><<<NN / 8, 256>>>(b3, fcW, fcb, (float*)d_out);

    cudaStreamDestroy(s2);
    cudaEventDestroy(evFork);
    cudaEventDestroy(evJoin);
    cudaEventDestroy(evW);
}